// round 8
// baseline (speedup 1.0000x reference)
#include <cuda_runtime.h>
#include <cuda_bf16.h>

// Problem constants (from reference): B=32, T=512, D=768, dur in [0,8]
#define LR_B 32
#define LR_T 512
#define LR_D 768
#define ZROWS 8   // output rows handled per zero-fill block

// ---------------------------------------------------------------------------
// Single fused kernel, R3 granularity.
//
// Scatter blocks (blockIdx.x < LR_T): block (s, b) expands source row s of
//   batch b. All 192 threads first issue the x-row streaming load (3KB).
//   Meanwhile warp 0 recomputes the batch's duration scan in registers
//   (512 floats, L2-hot: every block of the batch reads the same 2KB) and
//   publishes cum[s-1], cum[s] via smem. Then `reps` independent float4
//   streaming stores per thread. ~500 cycles of scan latency per block,
//   hidden under the chip-wide store stream (issue was only 18.6%).
//
// Zero-fill blocks (blockIdx.x >= LR_T): warp 0 warp-reduces tot[b]; block
//   zeroes its ZROWS output rows where t >= tot (out is 0xAA-poisoned).
//
// ONE launch: no scan kernel, no launch gap, no global scratch.
// ---------------------------------------------------------------------------
__global__ void __launch_bounds__(192) lr_fused_kernel(
    const float* __restrict__ x,
    const float* __restrict__ dur,
    float* __restrict__ out,
    int t_out)
{
    const int b   = blockIdx.y;
    const int tid = threadIdx.x;
    const int stride4 = LR_D / 4;          // 192 float4 per row
    const float* drow = dur + b * LR_T;

    if (blockIdx.x < LR_T) {
        // ------------------- scatter path -------------------
        const int s = blockIdx.x;
        __shared__ int s_prev, s_cs;

        // Issue the source-row load first (independent of the scan).
        const float4* xq = (const float4*)(x + ((size_t)b * LR_T + s) * LR_D) + tid;
        float4 v;
        asm volatile("ld.global.cs.v4.f32 {%0,%1,%2,%3}, [%4];"
                     : "=f"(v.x), "=f"(v.y), "=f"(v.z), "=f"(v.w)
                     : "l"(xq));

        if (tid < 32) {
            const int lane = tid;
            // register scan of 16 rounded durations per lane
            int vv[16];
            int run = 0;
            #pragma unroll
            for (int i = 0; i < 16; ++i) {
                float d = __ldg(drow + lane * 16 + i);
                run += (int)floorf(fmaxf(d, 0.0f) + 0.5f);  // identical fp ops to ref
                vv[i] = run;
            }
            // exclusive warp-scan of lane totals
            int total = run;
            #pragma unroll
            for (int st = 1; st < 32; st <<= 1) {
                int n = __shfl_up_sync(0xffffffff, total, st);
                if (lane >= st) total += n;
            }
            const int off = total - run;    // exclusive prefix of this lane

            // publish cum[s] and cum[s-1]
            if (lane == (s >> 4)) s_cs = vv[s & 15] + off;
            if (s == 0) {
                if (lane == 0) s_prev = 0;
            } else {
                if (lane == ((s - 1) >> 4)) s_prev = vv[(s - 1) & 15] + off;
            }
        }
        __syncthreads();

        const int prev = s_prev;
        const int reps = s_cs - prev;
        if (reps == 0) return;

        float4* obase = (float4*)(out + ((size_t)b * t_out + prev) * LR_D) + tid;
        #pragma unroll 4
        for (int r = 0; r < reps; ++r) {
            asm volatile("st.global.cs.v4.f32 [%0], {%1,%2,%3,%4};"
                         :: "l"(obase + (size_t)r * stride4),
                            "f"(v.x), "f"(v.y), "f"(v.z), "f"(v.w)
                         : "memory");
        }
    } else {
        // ------------------- zero-fill path -------------------
        __shared__ int s_tot;
        if (tid < 32) {
            const int lane = tid;
            int run = 0;
            #pragma unroll
            for (int i = 0; i < 16; ++i) {
                float d = __ldg(drow + lane * 16 + i);
                run += (int)floorf(fmaxf(d, 0.0f) + 0.5f);
            }
            #pragma unroll
            for (int st = 16; st >= 1; st >>= 1)
                run += __shfl_xor_sync(0xffffffff, run, st);
            if (lane == 0) s_tot = run;
        }
        __syncthreads();

        const int tot = s_tot;
        const int t0  = (blockIdx.x - LR_T) * ZROWS;
        if (t0 + ZROWS <= tot) return;      // fully inside valid region

        const float4 z = make_float4(0.f, 0.f, 0.f, 0.f);
        float4* ob = (float4*)(out + (size_t)b * t_out * LR_D) + tid;
        #pragma unroll
        for (int r = 0; r < ZROWS; ++r) {
            const int t = t0 + r;
            if (t >= tot && t < t_out) {
                asm volatile("st.global.cs.v4.f32 [%0], {%1,%2,%3,%4};"
                             :: "l"(ob + (size_t)t * stride4),
                                "f"(z.x), "f"(z.y), "f"(z.z), "f"(z.w)
                             : "memory");
            }
        }
    }
}

// ---------------------------------------------------------------------------
extern "C" void kernel_launch(void* const* d_in, const int* in_sizes, int n_in,
                              void* d_out, int out_size) {
    const float* x   = (const float*)d_in[0];   // [B, T, D] f32
    const float* dur = (const float*)d_in[1];   // [B, T]    f32
    float* out = (float*)d_out;                 // [B, t_out, D] f32

    const int t_out = out_size / (LR_B * LR_D);
    const int zero_blocks = (t_out + ZROWS - 1) / ZROWS;

    dim3 grid(LR_T + zero_blocks, LR_B);
    lr_fused_kernel<<<grid, 192>>>(x, dur, out, t_out);
}

// round 9
// speedup vs baseline: 1.1438x; 1.1438x over previous
#include <cuda_runtime.h>
#include <cuda_bf16.h>

// Problem constants (from reference): B=32, T=512, D=768, dur in [0,8]
#define LR_B 32
#define LR_T 512
#define LR_D 768
#define ZROWS 8   // output rows handled per zero-fill block
#define NTHR 192

// ---------------------------------------------------------------------------
// Single fused kernel, R3 granularity, cheap per-block prefix.
//
// Scatter block (s, b): all 192 threads issue the x-row streaming load first,
//   then cooperatively reduce cum[s] = sum_{j<=s} round(dur[b,j]) (<=3
//   coalesced L2-hot loads per thread + shfl warp-reduce + ONE barrier +
//   per-thread sum of 6 warp partials). prev = cum[s] - round(dur[b,s]).
//   Then `reps` independent float4 streaming stores per thread.
//
// Zero-fill block: same reduction over all 512 elements -> tot[b]; zero the
//   rows t >= tot in its ZROWS slice (out is 0xAA-poisoned).
//
// ONE launch: no scan kernel, no launch gap, no global scratch.
// ---------------------------------------------------------------------------
__device__ __forceinline__ int lr_round(float d) {
    return (int)floorf(fmaxf(d, 0.0f) + 0.5f);   // identical fp ops to reference
}

// Block-wide sum of round(drow[j]) for j in [0, n). One __syncthreads.
__device__ __forceinline__ int lr_block_prefix(const float* __restrict__ drow,
                                               int n, int tid) {
    __shared__ int wsum[NTHR / 32];
    int part = 0;
    #pragma unroll
    for (int j = tid; j < n; j += NTHR) part += lr_round(__ldg(drow + j));
    #pragma unroll
    for (int o = 16; o >= 1; o >>= 1) part += __shfl_xor_sync(0xffffffff, part, o);
    if ((tid & 31) == 0) wsum[tid >> 5] = part;
    __syncthreads();
    int c = 0;
    #pragma unroll
    for (int w = 0; w < NTHR / 32; ++w) c += wsum[w];
    return c;
}

__global__ void __launch_bounds__(NTHR) lr_fused_kernel(
    const float* __restrict__ x,
    const float* __restrict__ dur,
    float* __restrict__ out,
    int t_out)
{
    const int b   = blockIdx.y;
    const int tid = threadIdx.x;
    const int stride4 = LR_D / 4;          // 192 float4 per row
    const float* drow = dur + b * LR_T;

    if (blockIdx.x < LR_T) {
        // ------------------- scatter path -------------------
        const int s = blockIdx.x;

        // Issue the source-row load first (hides the prefix reduction).
        const float4* xq = (const float4*)(x + ((size_t)b * LR_T + s) * LR_D) + tid;
        float4 v;
        asm volatile("ld.global.cs.v4.f32 {%0,%1,%2,%3}, [%4];"
                     : "=f"(v.x), "=f"(v.y), "=f"(v.z), "=f"(v.w)
                     : "l"(xq));

        const int cs   = lr_block_prefix(drow, s + 1, tid);
        const int reps = lr_round(__ldg(drow + s));   // broadcast L1 hit
        if (reps == 0) return;
        const int prev = cs - reps;

        float4* obase = (float4*)(out + ((size_t)b * t_out + prev) * LR_D) + tid;
        #pragma unroll 4
        for (int r = 0; r < reps; ++r) {
            asm volatile("st.global.cs.v4.f32 [%0], {%1,%2,%3,%4};"
                         :: "l"(obase + (size_t)r * stride4),
                            "f"(v.x), "f"(v.y), "f"(v.z), "f"(v.w)
                         : "memory");
        }
    } else {
        // ------------------- zero-fill path -------------------
        const int tot = lr_block_prefix(drow, LR_T, tid);
        const int t0  = (blockIdx.x - LR_T) * ZROWS;
        if (t0 + ZROWS <= tot) return;      // fully inside valid region

        const float4 z = make_float4(0.f, 0.f, 0.f, 0.f);
        float4* ob = (float4*)(out + (size_t)b * t_out * LR_D) + tid;
        #pragma unroll
        for (int r = 0; r < ZROWS; ++r) {
            const int t = t0 + r;
            if (t >= tot && t < t_out) {
                asm volatile("st.global.cs.v4.f32 [%0], {%1,%2,%3,%4};"
                             :: "l"(ob + (size_t)t * stride4),
                                "f"(z.x), "f"(z.y), "f"(z.z), "f"(z.w)
                             : "memory");
            }
        }
    }
}

// ---------------------------------------------------------------------------
extern "C" void kernel_launch(void* const* d_in, const int* in_sizes, int n_in,
                              void* d_out, int out_size) {
    const float* x   = (const float*)d_in[0];   // [B, T, D] f32
    const float* dur = (const float*)d_in[1];   // [B, T]    f32
    float* out = (float*)d_out;                 // [B, t_out, D] f32

    const int t_out = out_size / (LR_B * LR_D);
    const int zero_blocks = (t_out + ZROWS - 1) / ZROWS;

    dim3 grid(LR_T + zero_blocks, LR_B);
    lr_fused_kernel<<<grid, NTHR>>>(x, dur, out, t_out);
}

// round 10
// speedup vs baseline: 1.1463x; 1.0022x over previous
#include <cuda_runtime.h>
#include <cuda_bf16.h>

// Problem constants (from reference): B=32, T=512, D=768, dur in [0,8]
#define LR_B 32
#define LR_T 512
#define LR_D 768
#define ZROWS 8   // output rows handled per zero-fill block
#define NTHR 192

// ---------------------------------------------------------------------------
// Single fused kernel, R3 granularity, vectorized per-block prefix.
//
// Scatter block (s, b): all 192 threads issue the x-row streaming load first,
//   then cooperatively reduce cum[s] = sum_{j<=s} round(dur[b,j]):
//   threads 0..127 each load ONE float4 of the 2KB dur row (coalesced,
//   L1/L2-hot), predicate the 4 elements on j < n, shfl warp-reduce, one
//   barrier, sum 6 warp partials. prev = cum[s] - round(dur[b,s]).
//   Then `reps` independent float4 streaming stores per thread.
//
// Zero-fill block: same reduction with n = 512 -> tot[b]; zero rows t >= tot
//   in its ZROWS slice (out is 0xAA-poisoned).
//
// ONE launch: no scan kernel, no launch gap, no global scratch.
// ---------------------------------------------------------------------------
__device__ __forceinline__ int lr_round(float d) {
    return (int)floorf(fmaxf(d, 0.0f) + 0.5f);   // identical fp ops to reference
}

// Block-wide sum of round(drow[j]) for j in [0, n), n <= 512.
// One float4 load per thread (tid < 128), one __syncthreads.
__device__ __forceinline__ int lr_block_prefix(const float* __restrict__ drow,
                                               int n, int tid) {
    __shared__ int wsum[NTHR / 32];
    int part = 0;
    if (tid < LR_T / 4) {
        const float4 d = __ldg((const float4*)drow + tid);
        const int base = tid * 4;
        if (base + 0 < n) part += lr_round(d.x);
        if (base + 1 < n) part += lr_round(d.y);
        if (base + 2 < n) part += lr_round(d.z);
        if (base + 3 < n) part += lr_round(d.w);
    }
    #pragma unroll
    for (int o = 16; o >= 1; o >>= 1) part += __shfl_xor_sync(0xffffffff, part, o);
    if ((tid & 31) == 0) wsum[tid >> 5] = part;
    __syncthreads();
    int c = 0;
    #pragma unroll
    for (int w = 0; w < NTHR / 32; ++w) c += wsum[w];
    return c;
}

__global__ void __launch_bounds__(NTHR) lr_fused_kernel(
    const float* __restrict__ x,
    const float* __restrict__ dur,
    float* __restrict__ out,
    int t_out)
{
    const int b   = blockIdx.y;
    const int tid = threadIdx.x;
    const int stride4 = LR_D / 4;          // 192 float4 per row
    const float* drow = dur + b * LR_T;

    if (blockIdx.x < LR_T) {
        // ------------------- scatter path -------------------
        const int s = blockIdx.x;

        // Issue the source-row load first (hides the prefix reduction).
        const float4* xq = (const float4*)(x + ((size_t)b * LR_T + s) * LR_D) + tid;
        float4 v;
        asm volatile("ld.global.cs.v4.f32 {%0,%1,%2,%3}, [%4];"
                     : "=f"(v.x), "=f"(v.y), "=f"(v.z), "=f"(v.w)
                     : "l"(xq));

        const int cs   = lr_block_prefix(drow, s + 1, tid);
        const int reps = lr_round(__ldg(drow + s));   // broadcast L1 hit
        if (reps == 0) return;
        const int prev = cs - reps;

        float4* obase = (float4*)(out + ((size_t)b * t_out + prev) * LR_D) + tid;
        #pragma unroll 4
        for (int r = 0; r < reps; ++r) {
            asm volatile("st.global.cs.v4.f32 [%0], {%1,%2,%3,%4};"
                         :: "l"(obase + (size_t)r * stride4),
                            "f"(v.x), "f"(v.y), "f"(v.z), "f"(v.w)
                         : "memory");
        }
    } else {
        // ------------------- zero-fill path -------------------
        const int tot = lr_block_prefix(drow, LR_T, tid);
        const int t0  = (blockIdx.x - LR_T) * ZROWS;
        if (t0 + ZROWS <= tot) return;      // fully inside valid region

        const float4 z = make_float4(0.f, 0.f, 0.f, 0.f);
        float4* ob = (float4*)(out + (size_t)b * t_out * LR_D) + tid;
        #pragma unroll
        for (int r = 0; r < ZROWS; ++r) {
            const int t = t0 + r;
            if (t >= tot && t < t_out) {
                asm volatile("st.global.cs.v4.f32 [%0], {%1,%2,%3,%4};"
                             :: "l"(ob + (size_t)t * stride4),
                                "f"(z.x), "f"(z.y), "f"(z.z), "f"(z.w)
                             : "memory");
            }
        }
    }
}

// ---------------------------------------------------------------------------
extern "C" void kernel_launch(void* const* d_in, const int* in_sizes, int n_in,
                              void* d_out, int out_size) {
    const float* x   = (const float*)d_in[0];   // [B, T, D] f32
    const float* dur = (const float*)d_in[1];   // [B, T]    f32
    float* out = (float*)d_out;                 // [B, t_out, D] f32

    const int t_out = out_size / (LR_B * LR_D);
    const int zero_blocks = (t_out + ZROWS - 1) / ZROWS;

    dim3 grid(LR_T + zero_blocks, LR_B);
    lr_fused_kernel<<<grid, NTHR>>>(x, dur, out, t_out);
}

// round 11
// speedup vs baseline: 1.1497x; 1.0029x over previous
#include <cuda_runtime.h>
#include <cuda_bf16.h>

// Problem constants (from reference): B=32, T=512, D=768, dur in [0, 8]
#define LR_B 32
#define LR_T 512
#define LR_D 768
#define ZROWS 32  // output rows handled per zero-fill block
#define NTHR 192
#define MAXREPS 8 // dur <= 8.0 -> round(dur) <= 8

// ---------------------------------------------------------------------------
// Single fused kernel (R9 structure — best measured, at HBM write ceiling).
//
// Scatter block (s, b): 192 threads issue the x-row streaming load first,
//   then cooperatively reduce cum[s] (scalar strided loads, L2-hot, shfl +
//   one barrier). prev = cum[s] - round(dur[b,s]). Then up to 8 predicated
//   independent float4 streaming stores per thread (reps <= 8 by DUR_MAX).
//
// Zero-fill block: unpredicated float4 reduction of all 512 durations ->
//   tot[b]; zeroes rows t >= tot in its ZROWS slice (out is 0xAA-poisoned).
// ---------------------------------------------------------------------------
__device__ __forceinline__ int lr_round(float d) {
    return (int)floorf(fmaxf(d, 0.0f) + 0.5f);   // identical fp ops to reference
}

__device__ __forceinline__ int lr_combine(int part, int tid) {
    __shared__ int wsum[NTHR / 32];
    #pragma unroll
    for (int o = 16; o >= 1; o >>= 1) part += __shfl_xor_sync(0xffffffff, part, o);
    if ((tid & 31) == 0) wsum[tid >> 5] = part;
    __syncthreads();
    int c = 0;
    #pragma unroll
    for (int w = 0; w < NTHR / 32; ++w) c += wsum[w];
    return c;
}

__global__ void __launch_bounds__(NTHR) lr_fused_kernel(
    const float* __restrict__ x,
    const float* __restrict__ dur,
    float* __restrict__ out,
    int t_out)
{
    const int b   = blockIdx.y;
    const int tid = threadIdx.x;
    const int stride4 = LR_D / 4;          // 192 float4 per row
    const float* drow = dur + b * LR_T;

    if (blockIdx.x < LR_T) {
        // ------------------- scatter path -------------------
        const int s = blockIdx.x;

        // Issue the source-row load first (hides the prefix reduction).
        const float4* xq = (const float4*)(x + ((size_t)b * LR_T + s) * LR_D) + tid;
        float4 v;
        asm volatile("ld.global.cs.v4.f32 {%0,%1,%2,%3}, [%4];"
                     : "=f"(v.x), "=f"(v.y), "=f"(v.z), "=f"(v.w)
                     : "l"(xq));

        // cum[s] = sum_{j<=s} round(drow[j]) : strided scalar loads (L2-hot).
        int part = 0;
        for (int j = tid; j <= s; j += NTHR) part += lr_round(__ldg(drow + j));
        const int cs   = lr_combine(part, tid);
        const int reps = lr_round(__ldg(drow + s));   // broadcast L1 hit
        if (reps == 0) return;
        const int prev = cs - reps;

        float4* obase = (float4*)(out + ((size_t)b * t_out + prev) * LR_D) + tid;
        // reps <= 8: fully unrolled, 8 independent predicated stores (MLP=8).
        #pragma unroll
        for (int r = 0; r < MAXREPS; ++r) {
            if (r < reps) {
                asm volatile("st.global.cs.v4.f32 [%0], {%1,%2,%3,%4};"
                             :: "l"(obase + (size_t)r * stride4),
                                "f"(v.x), "f"(v.y), "f"(v.z), "f"(v.w)
                             : "memory");
            }
        }
    } else {
        // ------------------- zero-fill path -------------------
        // tot[b]: unpredicated float4 reduce of all 512 durations.
        int part = 0;
        if (tid < LR_T / 4) {
            const float4 d = __ldg((const float4*)drow + tid);
            part = lr_round(d.x) + lr_round(d.y) + lr_round(d.z) + lr_round(d.w);
        }
        const int tot = lr_combine(part, tid);

        const int t0 = (blockIdx.x - LR_T) * ZROWS;
        if (t0 + ZROWS <= tot) return;      // fully inside valid region

        const float4 z = make_float4(0.f, 0.f, 0.f, 0.f);
        float4* ob = (float4*)(out + (size_t)b * t_out * LR_D) + tid;
        #pragma unroll 4
        for (int r = 0; r < ZROWS; ++r) {
            const int t = t0 + r;
            if (t >= tot && t < t_out) {
                asm volatile("st.global.cs.v4.f32 [%0], {%1,%2,%3,%4};"
                             :: "l"(ob + (size_t)t * stride4),
                                "f"(z.x), "f"(z.y), "f"(z.z), "f"(z.w)
                             : "memory");
            }
        }
    }
}

// ---------------------------------------------------------------------------
extern "C" void kernel_launch(void* const* d_in, const int* in_sizes, int n_in,
                              void* d_out, int out_size) {
    const float* x   = (const float*)d_in[0];   // [B, T, D] f32
    const float* dur = (const float*)d_in[1];   // [B, T]    f32
    float* out = (float*)d_out;                 // [B, t_out, D] f32

    const int t_out = out_size / (LR_B * LR_D);
    const int zero_blocks = (t_out + ZROWS - 1) / ZROWS;

    dim3 grid(LR_T + zero_blocks, LR_B);
    lr_fused_kernel<<<grid, NTHR>>>(x, dur, out, t_out);
}